// round 12
// baseline (speedup 1.0000x reference)
#include <cuda_runtime.h>
#include <cuda_fp16.h>

typedef unsigned int u32;

#define IMH 512
#define IMW 512
#define TW 128              // tile width (2 px per thread, 64 pairs/rowgroup)
#define TY 8
#define NCOLS 136           // TW + 8 halo
#define HALFC 68            // columns per parity
#define YPITCH 138          // luma pitch (halves)
#define NROWS 16            // TY + 8
#define NGRP 66             // odd-start 4-column groups per rowgroup
#define NGRPTOT  (8 * NGRP)    // 528 group builds per block
#define NTHREADS 544
#define CSTRIDE 544         // per-rank stride in parity column arrays (8*68)

// smem layout (bytes):
//  [sColE 19584][sColO 19584] = 39168
//  then EITHER [sY 4416][sUVE 4352][sUVO 4352] (phases 1-2b)
//  OR sGrp 76032 (row-major [group][36]) overlapping it (phases 2.5-3).
#define OFF_COLO 19584
#define OFF_Y    39168
#define OFF_UVE  (OFF_Y + YPITCH * NROWS * 2)    // 43584
#define OFF_UVO  (OFF_UVE + NROWS * HALFC * 4)   // 47936
#define OFF_GRP  39168
#define SMEM_TOTAL (OFF_GRP + 36 * NGRPTOT * 4)  // 115200

__device__ __forceinline__ void ce2(__half2& a, __half2& b) {
    __half2 lo = __hmin2(a, b);
    __half2 hi = __hmax2(a, b);
    a = lo;
    b = hi;
}

__device__ __forceinline__ __half2 u2h(u32 u) {
    __half2 h;
    *reinterpret_cast<u32*>(&h) = u;
    return h;
}
__device__ __forceinline__ u32 h2u(__half2 h) {
    return *reinterpret_cast<u32*>(&h);
}

// Batcher odd-even merge of two ascending sorted arrays (exact, any M,N).
// E = merge(evens), O = merge(odds); r0 = E0; CE(O[i], E[i+1]); tail by size.
// Correctness for general (M,N) verified by the 0-1 principle.
template <int M, int N>
struct OEM {
    static __device__ __forceinline__ void run(const __half2 (&a)[M],
                                               const __half2 (&b)[N],
                                               __half2 (&r)[M + N]) {
        if constexpr (M == 1 && N == 1) {
            r[0] = __hmin2(a[0], b[0]);
            r[1] = __hmax2(a[0], b[0]);
        } else {
            constexpr int ME = (M + 1) / 2, MO = M / 2;
            constexpr int NE = (N + 1) / 2, NO = N / 2;
            constexpr int LE = ME + NE, LO = MO + NO;
            __half2 ae[ME], be[NE];
#pragma unroll
            for (int i = 0; i < ME; i++) ae[i] = a[2 * i];
#pragma unroll
            for (int i = 0; i < NE; i++) be[i] = b[2 * i];
            __half2 E[LE];
            OEM<ME, NE>::run(ae, be, E);
            __half2 O[LO];
            if constexpr (MO > 0 && NO > 0) {
                __half2 ao[MO], bo[NO];
#pragma unroll
                for (int i = 0; i < MO; i++) ao[i] = a[2 * i + 1];
#pragma unroll
                for (int i = 0; i < NO; i++) bo[i] = b[2 * i + 1];
                OEM<MO, NO>::run(ao, bo, O);
            } else if constexpr (MO > 0) {
#pragma unroll
                for (int i = 0; i < MO; i++) O[i] = a[2 * i + 1];
            } else {
#pragma unroll
                for (int i = 0; i < NO; i++) O[i] = b[2 * i + 1];
            }
            r[0] = E[0];
            constexpr int K = (LO < LE - 1) ? LO : LE - 1;
#pragma unroll
            for (int i = 0; i < K; i++) {
                r[2 * i + 1] = __hmin2(O[i], E[i + 1]);
                r[2 * i + 2] = __hmax2(O[i], E[i + 1]);
            }
            if constexpr (LE == LO) r[M + N - 1] = O[LO - 1];
            else if constexpr (LE == LO + 2) r[M + N - 1] = E[LE - 1];
        }
    }
};

// sort9 in 27 CEs: 3x sort3, OEM(3,3)->6, OEM(6,3)->9.
__device__ __forceinline__ void sort9(__half2 (&v)[9]) {
#pragma unroll
    for (int b = 0; b < 9; b += 3) {
        ce2(v[b], v[b + 1]); ce2(v[b + 1], v[b + 2]); ce2(v[b], v[b + 1]);
    }
    __half2 a3[3] = {v[0], v[1], v[2]};
    __half2 b3[3] = {v[3], v[4], v[5]};
    __half2 s6[6];
    OEM<3, 3>::run(a3, b3, s6);
    __half2 c3[3] = {v[6], v[7], v[8]};
    __half2 s9[9];
    OEM<6, 3>::run(s6, c3, s9);
#pragma unroll
    for (int k = 0; k < 9; k++) v[k] = s9[k];
}

__device__ __forceinline__ int reflect_idx(int i, int n) {
    if (i < 0) i = -1 - i;          // numpy 'symmetric'
    if (i >= n) i = 2 * n - 1 - i;
    return i;
}

__global__ void __launch_bounds__(NTHREADS, 2)
denoise_median_kernel(const float* __restrict__ img, float* __restrict__ out) {
    extern __shared__ char smem_raw[];
    __half2* sColE = (__half2*)smem_raw;                 // [rank][rg*68+m]
    __half2* sColO = (__half2*)(smem_raw + OFF_COLO);
    __half*  sYh   = (__half*)(smem_raw + OFF_Y);        // luma fp16, +1 shift
    __half2* sUVE  = (__half2*)(smem_raw + OFF_UVE);     // even cols (U,V)
    __half2* sUVO  = (__half2*)(smem_raw + OFF_UVO);     // odd cols
    __half2* sGrp  = (__half2*)(smem_raw + OFF_GRP);     // [group][36]

    const int bx = blockIdx.x * TW;
    const int by = blockIdx.y * TY;
    const int bat = blockIdx.z;
    const int tid = threadIdx.x;

    const float* Rp = img + (size_t)bat * 3 * IMH * IMW;
    const float* Gp = Rp + IMH * IMW;
    const float* Bp = Gp + IMH * IMW;

    const int mm = tid % HALFC;       // parity-column pair index
    const int rr8 = tid / HALFC;      // 0..7

    // ---- Phase 1: load halo tile via float2 (pairs survive reflection) ----
    {
        // x pair: columns (2mm, 2mm+1). Pair start even -> never straddles a
        // reflection seam; reflected pairs are adjacent-swapped.
        int i0 = bx - 4 + 2 * mm;
        bool rev = false;
        int gx0 = i0;
        if (i0 < 0) { gx0 = -2 - i0; rev = true; }
        else if (i0 >= IMW) { gx0 = 2 * IMW - 2 - i0; rev = true; }
#pragma unroll
        for (int it = 0; it < 2; it++) {
            int r = it * 8 + rr8;
            int gy = reflect_idx(by - 4 + r, IMH);
            size_t rowoff = (size_t)gy * IMW + gx0;
            float2 fr = *(const float2*)(Rp + rowoff);
            float2 fg = *(const float2*)(Gp + rowoff);
            float2 fb = *(const float2*)(Bp + rowoff);
            float R0 = rev ? fr.y : fr.x, R1 = rev ? fr.x : fr.y;
            float G0 = rev ? fg.y : fg.x, G1 = rev ? fg.x : fg.y;
            float B0 = rev ? fb.y : fb.x, B1 = rev ? fb.x : fb.y;
            float Y0 = 0.299f * R0 + 0.587f * G0 + 0.114f * B0;
            float Y1 = 0.299f * R1 + 0.587f * G1 + 0.114f * B1;
            float U0 = -0.14713f * R0 - 0.28886f * G0 + 0.436f * B0;
            float U1 = -0.14713f * R1 - 0.28886f * G1 + 0.436f * B1;
            float V0 = 0.615f * R0 - 0.51499f * G0 - 0.10001f * B0;
            float V1 = 0.615f * R1 - 0.51499f * G1 - 0.10001f * B1;
            sYh[r * YPITCH + 2 * mm + 1] = __float2half(Y0);
            sYh[r * YPITCH + 2 * mm + 2] = __float2half(Y1);
            sUVE[r * HALFC + mm] = __floats2half2_rn(U0, V0);
            sUVO[r * HALFC + mm] = __floats2half2_rn(U1, V1);
        }
    }
    __syncthreads();

    const int tp = tid & 63;          // pixel-pair index within rowgroup
    const int ty = tid >> 6;          // rowgroup (valid for tid < 512)
    const int c0 = 2 * tp;            // left pixel's local halo column

    // ---- Phase 2a: luma (both pixels, one half2 3x3 network) -> registers ----
    __half2 ylum2;
    if (tid < 512) {
        __half2 pl[9];
#pragma unroll
        for (int rw = 0; rw < 3; rw++) {
            const u32* wp =
                (const u32*)(sYh + (ty + 3 + rw) * YPITCH + c0 + 4);
            u32 w0 = wp[0];
            u32 w1 = wp[1];
            pl[rw * 3 + 0] = u2h(w0);
            pl[rw * 3 + 1] = u2h(__byte_perm(w0, w1, 0x5432));
            pl[rw * 3 + 2] = u2h(w1);
        }
        ce2(pl[1], pl[2]); ce2(pl[4], pl[5]); ce2(pl[7], pl[8]);
        ce2(pl[0], pl[1]); ce2(pl[3], pl[4]); ce2(pl[6], pl[7]);
        ce2(pl[1], pl[2]); ce2(pl[4], pl[5]); ce2(pl[7], pl[8]);
        ce2(pl[0], pl[3]); ce2(pl[5], pl[8]); ce2(pl[4], pl[7]);
        ce2(pl[3], pl[6]); ce2(pl[1], pl[4]); ce2(pl[2], pl[5]);
        ce2(pl[4], pl[7]); ce2(pl[4], pl[2]); ce2(pl[6], pl[4]);
        ce2(pl[4], pl[2]);
        ylum2 = __hmin2(__hmax2(pl[4], __floats2half2_rn(0.f, 0.f)),
                        __floats2half2_rn(1.f, 1.f));
    }

    // ---- Phase 2b: sorted 9-columns; exactly 2 per thread, conflict-free ----
#pragma unroll
    for (int it = 0; it < 2; it++) {
        const __half2* src = it ? sUVO : sUVE;
        __half2* dst = it ? sColO : sColE;
        __half2 v[9];
#pragma unroll
        for (int k = 0; k < 9; k++) v[k] = src[(rr8 + k) * HALFC + mm];
        sort9(v);
#pragma unroll
        for (int k = 0; k < 9; k++) dst[k * CSTRIDE + tid] = v[k];
    }
    __syncthreads();   // Y/UV dead from here; sGrp overwrites them

    // ---- Phase 2.5: sorted-36 groups of 4 columns; <=1 per thread ----
    if (tid < NGRPTOT) {
        const int rg = tid / NGRP;
        const int g = tid % NGRP;
        const int cb = rg * HALFC;
        // cols s..s+3 = odd(g), even(g+1), odd(g+1), even(g+2)
        __half2 ca[9], cb9[9], cc[9], cd[9];
#pragma unroll
        for (int k = 0; k < 9; k++) {
            ca[k]  = sColO[k * CSTRIDE + cb + g];
            cb9[k] = sColE[k * CSTRIDE + cb + g + 1];
            cc[k]  = sColO[k * CSTRIDE + cb + g + 1];
            cd[k]  = sColE[k * CSTRIDE + cb + g + 2];
        }
        __half2 m0[18], m1[18];
        OEM<9, 9>::run(ca, cb9, m0);
        OEM<9, 9>::run(cc, cd, m1);
        __half2 A[36];
        OEM<18, 18>::run(m0, m1, A);
        uint4* dst = reinterpret_cast<uint4*>(sGrp + tid * 36);
#pragma unroll
        for (int q = 0; q < 9; q++) {
            uint4 u;
            u.x = h2u(A[4 * q + 0]);
            u.y = h2u(A[4 * q + 1]);
            u.z = h2u(A[4 * q + 2]);
            u.w = h2u(A[4 * q + 3]);
            dst[q] = u;
        }
    }
    __syncthreads();

    if (tid >= 512) return;

    // ---- Phase 3: OEM(36,36) of the two shared groups, DCE-pruned ----
    const int gAi = ty * NGRP + tp;       // cols c0+1..c0+4
    const int gBi = gAi + 2;              // cols c0+5..c0+8

    __half2 A36[36], B36[36];
    {
        const uint4* pa = reinterpret_cast<const uint4*>(sGrp + gAi * 36);
#pragma unroll
        for (int q = 0; q < 9; q++) {
            uint4 u = pa[q];
            A36[4 * q + 0] = u2h(u.x);
            A36[4 * q + 1] = u2h(u.y);
            A36[4 * q + 2] = u2h(u.z);
            A36[4 * q + 3] = u2h(u.w);
        }
        const uint4* pb = reinterpret_cast<const uint4*>(sGrp + gBi * 36);
#pragma unroll
        for (int q = 0; q < 9; q++) {
            uint4 u = pb[q];
            B36[4 * q + 0] = u2h(u.x);
            B36[4 * q + 1] = u2h(u.y);
            B36[4 * q + 2] = u2h(u.z);
            B36[4 * q + 3] = u2h(u.w);
        }
    }
    __half2 T[72];
    OEM<36, 36>::run(A36, B36, T);   // only ranks 31..40 consumed -> DCE prunes

    // ---- Per-pixel: add private column via rank-40 selection identity ----
    // merged[40] = max_{i+j=40} min(T[i], col[j]), OOR -> +inf.
    const int cbE = ty * HALFC + tp;       // colL = even col, m=tp
    const int cbO = ty * HALFC + tp + 4;   // colR = odd col 2tp+9, m=tp+4
    __half2 mL = T[31], mR = T[31];
#pragma unroll
    for (int k = 1; k <= 9; k++) {
        mL = __hmax2(mL, __hmin2(T[31 + k], sColE[(9 - k) * CSTRIDE + cbE]));
        mR = __hmax2(mR, __hmin2(T[31 + k], sColO[(9 - k) * CSTRIDE + cbO]));
    }

    // ---- YUV -> RGB, vectorized pair store ----
    float ylumL = __low2float(ylum2);
    float ylumR = __high2float(ylum2);
    float uL = __low2float(mL), vL = __high2float(mL);
    float uR = __low2float(mR), vR = __high2float(mR);

    float2 Rv = make_float2(ylumL + 1.13983f * vL, ylumR + 1.13983f * vR);
    float2 Gv = make_float2(ylumL - 0.39465f * uL - 0.5806f * vL,
                            ylumR - 0.39465f * uR - 0.5806f * vR);
    float2 Bv = make_float2(ylumL + 2.03211f * uL, ylumR + 2.03211f * uR);

    const int gy = by + ty;
    const int gx = bx + c0;
    size_t o = (size_t)bat * 3 * IMH * IMW + (size_t)gy * IMW + gx;
    *(float2*)(out + o) = Rv;
    *(float2*)(out + o + IMH * IMW) = Gv;
    *(float2*)(out + o + 2 * IMH * IMW) = Bv;
}

extern "C" void kernel_launch(void* const* d_in, const int* in_sizes, int n_in,
                              void* d_out, int out_size) {
    const float* img = (const float*)d_in[0];
    float* out = (float*)d_out;
    int batch = in_sizes[0] / (3 * IMH * IMW);
    cudaFuncSetAttribute(denoise_median_kernel,
                         cudaFuncAttributeMaxDynamicSharedMemorySize, SMEM_TOTAL);
    dim3 grid(IMW / TW, IMH / TY, batch);
    denoise_median_kernel<<<grid, NTHREADS, SMEM_TOTAL>>>(img, out);
}

// round 13
// speedup vs baseline: 1.0831x; 1.0831x over previous
#include <cuda_runtime.h>
#include <cuda_fp16.h>

typedef unsigned int u32;

#define IMH 512
#define IMW 512
#define TW 128              // tile width (2 px per thread, 64 pairs/rowgroup)
#define TY 8
#define NCOLS 136           // TW + 8 halo
#define HALFC 68            // columns per parity
#define YPITCH 138          // luma pitch (halves)
#define NROWS 16            // TY + 8
#define NGRP 66             // odd-start 4-column groups per rowgroup
#define NGRPTOT  (8 * NGRP)    // 528 group builds per block
#define NTHREADS 544
#define CSTRIDE 544         // per-rank stride in parity column arrays (8*68)

// smem layout (bytes):
//  [sColE 19584][sColO 19584] = 39168
//  then EITHER [sY 4416][sUVE 4352][sUVO 4352] (phases 1-2b)
//  OR sGrp 76032 (row-major [group][36]) overlapping it (phases 2.5-3).
#define OFF_COLO 19584
#define OFF_Y    39168
#define OFF_UVE  (OFF_Y + YPITCH * NROWS * 2)    // 43584
#define OFF_UVO  (OFF_UVE + NROWS * HALFC * 4)   // 47936
#define OFF_GRP  39168
#define SMEM_TOTAL (OFF_GRP + 36 * NGRPTOT * 4)  // 115200

__device__ __forceinline__ void ce2(__half2& a, __half2& b) {
    __half2 lo = __hmin2(a, b);
    __half2 hi = __hmax2(a, b);
    a = lo;
    b = hi;
}

__device__ __forceinline__ __half2 u2h(u32 u) {
    __half2 h;
    *reinterpret_cast<u32*>(&h) = u;
    return h;
}
__device__ __forceinline__ u32 h2u(__half2 h) {
    return *reinterpret_cast<u32*>(&h);
}

// Ascending bitonic merge stages over t[0..L) with virtual +inf padding to the
// next power of two. Input must be bitonic: [descending | ascending | +inf...].
template <int L, int S>
__device__ __forceinline__ void bstages(__half2 (&t)[L]) {
    if constexpr (S >= 1) {
#pragma unroll
        for (int i = 0; i + S < L; i++)
            if ((i & S) == 0) ce2(t[i], t[i + S]);
        bstages<L, S / 2>(t);
    }
}

// sort9 in 29 CEs: 3x sort3, merge(3,3)->6, merge(6,3)->9.
__device__ __forceinline__ void sort9(__half2 (&v)[9]) {
#pragma unroll
    for (int b = 0; b < 9; b += 3) {
        ce2(v[b], v[b + 1]); ce2(v[b + 1], v[b + 2]); ce2(v[b], v[b + 1]);
    }
    __half2 m[6] = {v[2], v[1], v[0], v[3], v[4], v[5]};   // [desc3 | asc3]
    bstages<6, 4>(m);
    __half2 t[9] = {m[5], m[4], m[3], m[2], m[1], m[0],    // [desc6 | asc3]
                    v[6], v[7], v[8]};
    bstages<9, 8>(t);
#pragma unroll
    for (int k = 0; k < 9; k++) v[k] = t[k];
}

__device__ __forceinline__ int reflect_idx(int i, int n) {
    if (i < 0) i = -1 - i;          // numpy 'symmetric'
    if (i >= n) i = 2 * n - 1 - i;
    return i;
}

__global__ void __launch_bounds__(NTHREADS, 2)
denoise_median_kernel(const float* __restrict__ img, float* __restrict__ out) {
    extern __shared__ char smem_raw[];
    __half2* sColE = (__half2*)smem_raw;                 // [rank][rg*68+m]
    __half2* sColO = (__half2*)(smem_raw + OFF_COLO);
    __half*  sYh   = (__half*)(smem_raw + OFF_Y);        // luma fp16, +1 shift
    __half2* sUVE  = (__half2*)(smem_raw + OFF_UVE);     // even cols (U,V)
    __half2* sUVO  = (__half2*)(smem_raw + OFF_UVO);     // odd cols
    __half2* sGrp  = (__half2*)(smem_raw + OFF_GRP);     // [group][36]

    const int bx = blockIdx.x * TW;
    const int by = blockIdx.y * TY;
    const int bat = blockIdx.z;
    const int tid = threadIdx.x;

    const float* Rp = img + (size_t)bat * 3 * IMH * IMW;
    const float* Gp = Rp + IMH * IMW;
    const float* Bp = Gp + IMH * IMW;

    const int mm = tid % HALFC;       // parity-column pair index
    const int rr8 = tid / HALFC;      // 0..7

    // ---- Phase 1: load halo tile via float2 (pairs survive reflection) ----
    {
        // x pair: columns (2mm, 2mm+1). Pair start even -> never straddles a
        // reflection seam; reflected pairs are adjacent-swapped.
        int i0 = bx - 4 + 2 * mm;
        bool rev = false;
        int gx0 = i0;
        if (i0 < 0) { gx0 = -2 - i0; rev = true; }
        else if (i0 >= IMW) { gx0 = 2 * IMW - 2 - i0; rev = true; }
#pragma unroll
        for (int it = 0; it < 2; it++) {
            int r = it * 8 + rr8;
            int gy = reflect_idx(by - 4 + r, IMH);
            size_t rowoff = (size_t)gy * IMW + gx0;
            float2 fr = *(const float2*)(Rp + rowoff);
            float2 fg = *(const float2*)(Gp + rowoff);
            float2 fb = *(const float2*)(Bp + rowoff);
            float R0 = rev ? fr.y : fr.x, R1 = rev ? fr.x : fr.y;
            float G0 = rev ? fg.y : fg.x, G1 = rev ? fg.x : fg.y;
            float B0 = rev ? fb.y : fb.x, B1 = rev ? fb.x : fb.y;
            float Y0 = 0.299f * R0 + 0.587f * G0 + 0.114f * B0;
            float Y1 = 0.299f * R1 + 0.587f * G1 + 0.114f * B1;
            float U0 = -0.14713f * R0 - 0.28886f * G0 + 0.436f * B0;
            float U1 = -0.14713f * R1 - 0.28886f * G1 + 0.436f * B1;
            float V0 = 0.615f * R0 - 0.51499f * G0 - 0.10001f * B0;
            float V1 = 0.615f * R1 - 0.51499f * G1 - 0.10001f * B1;
            sYh[r * YPITCH + 2 * mm + 1] = __float2half(Y0);
            sYh[r * YPITCH + 2 * mm + 2] = __float2half(Y1);
            sUVE[r * HALFC + mm] = __floats2half2_rn(U0, V0);
            sUVO[r * HALFC + mm] = __floats2half2_rn(U1, V1);
        }
    }
    __syncthreads();

    const int tp = tid & 63;          // pixel-pair index within rowgroup
    const int ty = tid >> 6;          // rowgroup (valid for tid < 512)
    const int c0 = 2 * tp;            // left pixel's local halo column

    // ---- Phase 2a: luma (both pixels, one half2 3x3 network) -> registers ----
    __half2 ylum2;
    if (tid < 512) {
        __half2 pl[9];
#pragma unroll
        for (int rw = 0; rw < 3; rw++) {
            const u32* wp =
                (const u32*)(sYh + (ty + 3 + rw) * YPITCH + c0 + 4);
            u32 w0 = wp[0];
            u32 w1 = wp[1];
            pl[rw * 3 + 0] = u2h(w0);
            pl[rw * 3 + 1] = u2h(__byte_perm(w0, w1, 0x5432));
            pl[rw * 3 + 2] = u2h(w1);
        }
        ce2(pl[1], pl[2]); ce2(pl[4], pl[5]); ce2(pl[7], pl[8]);
        ce2(pl[0], pl[1]); ce2(pl[3], pl[4]); ce2(pl[6], pl[7]);
        ce2(pl[1], pl[2]); ce2(pl[4], pl[5]); ce2(pl[7], pl[8]);
        ce2(pl[0], pl[3]); ce2(pl[5], pl[8]); ce2(pl[4], pl[7]);
        ce2(pl[3], pl[6]); ce2(pl[1], pl[4]); ce2(pl[2], pl[5]);
        ce2(pl[4], pl[7]); ce2(pl[4], pl[2]); ce2(pl[6], pl[4]);
        ce2(pl[4], pl[2]);
        ylum2 = __hmin2(__hmax2(pl[4], __floats2half2_rn(0.f, 0.f)),
                        __floats2half2_rn(1.f, 1.f));
    }

    // ---- Phase 2b: sorted 9-columns; exactly 2 per thread, conflict-free ----
#pragma unroll
    for (int it = 0; it < 2; it++) {
        const __half2* src = it ? sUVO : sUVE;
        __half2* dst = it ? sColO : sColE;
        __half2 v[9];
#pragma unroll
        for (int k = 0; k < 9; k++) v[k] = src[(rr8 + k) * HALFC + mm];
        sort9(v);
#pragma unroll
        for (int k = 0; k < 9; k++) dst[k * CSTRIDE + tid] = v[k];
    }
    __syncthreads();   // Y/UV dead from here; sGrp overwrites them

    // ---- Phase 2.5: sorted-36 groups of 4 columns; <=1 per thread ----
    if (tid < NGRPTOT) {
        const int rg = tid / NGRP;
        const int g = tid % NGRP;
        const int cb = rg * HALFC;
        // cols s..s+3 = odd(g), even(g+1), odd(g+1), even(g+2)
        __half2 r0[18], r1[18];
#pragma unroll
        for (int k = 0; k < 9; k++) {
            r0[k]     = sColO[(8 - k) * CSTRIDE + cb + g];        // desc
            r0[9 + k] = sColE[k * CSTRIDE + cb + g + 1];          // asc
            r1[k]     = sColO[(8 - k) * CSTRIDE + cb + g + 1];
            r1[9 + k] = sColE[k * CSTRIDE + cb + g + 2];
        }
        bstages<18, 16>(r0);
        bstages<18, 16>(r1);
        __half2 A[36];
#pragma unroll
        for (int k = 0; k < 18; k++) {
            A[k]      = r0[17 - k];
            A[18 + k] = r1[k];
        }
        bstages<36, 32>(A);
        uint4* dst = reinterpret_cast<uint4*>(sGrp + tid * 36);
#pragma unroll
        for (int q = 0; q < 9; q++) {
            uint4 u;
            u.x = h2u(A[4 * q + 0]);
            u.y = h2u(A[4 * q + 1]);
            u.z = h2u(A[4 * q + 2]);
            u.w = h2u(A[4 * q + 3]);
            dst[q] = u;
        }
    }
    __syncthreads();

    if (tid >= 512) return;

    // ---- Phase 3: pruned 72-merge of the two shared groups ----
    const int gAi = ty * NGRP + tp;       // cols c0+1..c0+4
    const int gBi = gAi + 2;              // cols c0+5..c0+8

    __half2 T[72];
    {
        const uint4* pa = reinterpret_cast<const uint4*>(sGrp + gAi * 36);
#pragma unroll
        for (int q = 0; q < 9; q++) {
            uint4 u = pa[q];
            T[35 - (4 * q + 0)] = u2h(u.x);    // descending half
            T[35 - (4 * q + 1)] = u2h(u.y);
            T[35 - (4 * q + 2)] = u2h(u.z);
            T[35 - (4 * q + 3)] = u2h(u.w);
        }
        const uint4* pb = reinterpret_cast<const uint4*>(sGrp + gBi * 36);
#pragma unroll
        for (int q = 0; q < 9; q++) {
            uint4 u = pb[q];
            T[36 + 4 * q + 0] = u2h(u.x);      // ascending half
            T[36 + 4 * q + 1] = u2h(u.y);
            T[36 + 4 * q + 2] = u2h(u.z);
            T[36 + 4 * q + 3] = u2h(u.w);
        }
    }
    bstages<72, 64>(T);   // only ranks 31..40 consumed -> DCE prunes cone

    // ---- Per-pixel: add private column via rank-40 selection identity ----
    // merged[40] = max_{i+j=40} min(T[i], col[j]), OOR -> +inf.
    const int cbE = ty * HALFC + tp;       // colL = even col, m=tp
    const int cbO = ty * HALFC + tp + 4;   // colR = odd col 2tp+9, m=tp+4
    __half2 mL = T[31], mR = T[31];
#pragma unroll
    for (int k = 1; k <= 9; k++) {
        mL = __hmax2(mL, __hmin2(T[31 + k], sColE[(9 - k) * CSTRIDE + cbE]));
        mR = __hmax2(mR, __hmin2(T[31 + k], sColO[(9 - k) * CSTRIDE + cbO]));
    }

    // ---- YUV -> RGB, vectorized pair store ----
    float ylumL = __low2float(ylum2);
    float ylumR = __high2float(ylum2);
    float uL = __low2float(mL), vL = __high2float(mL);
    float uR = __low2float(mR), vR = __high2float(mR);

    float2 Rv = make_float2(ylumL + 1.13983f * vL, ylumR + 1.13983f * vR);
    float2 Gv = make_float2(ylumL - 0.39465f * uL - 0.5806f * vL,
                            ylumR - 0.39465f * uR - 0.5806f * vR);
    float2 Bv = make_float2(ylumL + 2.03211f * uL, ylumR + 2.03211f * uR);

    const int gy = by + ty;
    const int gx = bx + c0;
    size_t o = (size_t)bat * 3 * IMH * IMW + (size_t)gy * IMW + gx;
    *(float2*)(out + o) = Rv;
    *(float2*)(out + o + IMH * IMW) = Gv;
    *(float2*)(out + o + 2 * IMH * IMW) = Bv;
}

extern "C" void kernel_launch(void* const* d_in, const int* in_sizes, int n_in,
                              void* d_out, int out_size) {
    const float* img = (const float*)d_in[0];
    float* out = (float*)d_out;
    int batch = in_sizes[0] / (3 * IMH * IMW);
    cudaFuncSetAttribute(denoise_median_kernel,
                         cudaFuncAttributeMaxDynamicSharedMemorySize, SMEM_TOTAL);
    dim3 grid(IMW / TW, IMH / TY, batch);
    denoise_median_kernel<<<grid, NTHREADS, SMEM_TOTAL>>>(img, out);
}